// round 1
// baseline (speedup 1.0000x reference)
#include <cuda_runtime.h>

#define NN   512
#define CZc  128
#define RTOT (NN*NN)

// Scratch (device globals; no allocations allowed)
__device__ float g_a  [(size_t)RTOT * CZc];
__device__ float g_b  [(size_t)RTOT * CZc];
__device__ float g_g  [(size_t)RTOT * CZc];
__device__ float g_upd[(size_t)RTOT * CZc];

__device__ __forceinline__ float sigmoidf(float x) {
    return 1.0f / (1.0f + __expf(-x));
}

// ---------------------------------------------------------------------------
// Kernel 1: fused LN1 + 5 projections (+ sigmoid gating) -> g_a, g_b, g_g
// 256 threads, 32 rows/block, 8192 blocks.
// ---------------------------------------------------------------------------
__global__ __launch_bounds__(256, 4) void k_proj(
    const float* __restrict__ x,
    const float* __restrict__ gamma,
    const float* __restrict__ beta,
    const float* __restrict__ wga,
    const float* __restrict__ wgb,
    const float* __restrict__ wa,
    const float* __restrict__ wb,
    const float* __restrict__ wg)
{
    __shared__ float zs[32 * CZc];
    const int tid  = threadIdx.x;
    const int base = blockIdx.x * (32 * CZc);

    // Load 32x128 tile (fully coalesced)
    for (int t = tid; t < 32 * CZc; t += 256) zs[t] = x[base + t];
    __syncthreads();

    // LayerNorm: 8 warps x 4 rows, warp-shuffle reduction
    {
        const int w = tid >> 5, lane = tid & 31;
        #pragma unroll
        for (int rr = 0; rr < 4; ++rr) {
            const int row = w * 4 + rr;
            const float v0 = zs[row * CZc + lane];
            const float v1 = zs[row * CZc + lane + 32];
            const float v2 = zs[row * CZc + lane + 64];
            const float v3 = zs[row * CZc + lane + 96];
            float s  = v0 + v1 + v2 + v3;
            float s2 = v0*v0 + v1*v1 + v2*v2 + v3*v3;
            #pragma unroll
            for (int o = 16; o; o >>= 1) {
                s  += __shfl_xor_sync(0xffffffffu, s,  o);
                s2 += __shfl_xor_sync(0xffffffffu, s2, o);
            }
            const float mu   = s * (1.0f / CZc);
            const float var  = s2 * (1.0f / CZc) - mu * mu;
            const float rstd = rsqrtf(var + 1e-5f);
            zs[row*CZc + lane     ] = (v0-mu)*rstd*gamma[lane     ] + beta[lane     ];
            zs[row*CZc + lane + 32] = (v1-mu)*rstd*gamma[lane + 32] + beta[lane + 32];
            zs[row*CZc + lane + 64] = (v2-mu)*rstd*gamma[lane + 64] + beta[lane + 64];
            zs[row*CZc + lane + 96] = (v3-mu)*rstd*gamma[lane + 96] + beta[lane + 96];
        }
    }
    __syncthreads();

    const int ty = tid >> 5;   // 0..7 : row group (4 rows)
    const int tx = tid & 31;   // 0..31: col group (4 cols)
    const int r0 = ty * 4;
    const int cb = tx * 4;

    // Two gated passes: (wga, wa) -> g_a ; (wgb, wb) -> g_b
    for (int pass = 0; pass < 2; ++pass) {
        const float* __restrict__ Wg = pass ? wgb : wga;
        const float* __restrict__ Wl = pass ? wb  : wa;
        float* __restrict__ Out      = pass ? g_b : g_a;

        float ag[4][4], al[4][4];
        #pragma unroll
        for (int r = 0; r < 4; ++r)
            #pragma unroll
            for (int c = 0; c < 4; ++c) { ag[r][c] = 0.f; al[r][c] = 0.f; }

        #pragma unroll 4
        for (int k = 0; k < CZc; ++k) {
            float z[4];
            #pragma unroll
            for (int r = 0; r < 4; ++r) z[r] = zs[(r0 + r) * CZc + k];
            const float4 wg4 = *(const float4*)(Wg + k * CZc + cb);
            const float4 wl4 = *(const float4*)(Wl + k * CZc + cb);
            #pragma unroll
            for (int r = 0; r < 4; ++r) {
                ag[r][0] += z[r] * wg4.x;  ag[r][1] += z[r] * wg4.y;
                ag[r][2] += z[r] * wg4.z;  ag[r][3] += z[r] * wg4.w;
                al[r][0] += z[r] * wl4.x;  al[r][1] += z[r] * wl4.y;
                al[r][2] += z[r] * wl4.z;  al[r][3] += z[r] * wl4.w;
            }
        }
        #pragma unroll
        for (int r = 0; r < 4; ++r) {
            float4 o;
            o.x = sigmoidf(ag[r][0]) * al[r][0];
            o.y = sigmoidf(ag[r][1]) * al[r][1];
            o.z = sigmoidf(ag[r][2]) * al[r][2];
            o.w = sigmoidf(ag[r][3]) * al[r][3];
            *(float4*)(Out + base + (r0 + r) * CZc + cb) = o;
        }
    }

    // Gate pass: sigmoid(z @ w_gate) -> g_g
    {
        float ac[4][4];
        #pragma unroll
        for (int r = 0; r < 4; ++r)
            #pragma unroll
            for (int c = 0; c < 4; ++c) ac[r][c] = 0.f;

        #pragma unroll 4
        for (int k = 0; k < CZc; ++k) {
            float z[4];
            #pragma unroll
            for (int r = 0; r < 4; ++r) z[r] = zs[(r0 + r) * CZc + k];
            const float4 w4 = *(const float4*)(wg + k * CZc + cb);
            #pragma unroll
            for (int r = 0; r < 4; ++r) {
                ac[r][0] += z[r] * w4.x;  ac[r][1] += z[r] * w4.y;
                ac[r][2] += z[r] * w4.z;  ac[r][3] += z[r] * w4.w;
            }
        }
        #pragma unroll
        for (int r = 0; r < 4; ++r) {
            float4 o;
            o.x = sigmoidf(ac[r][0]);
            o.y = sigmoidf(ac[r][1]);
            o.z = sigmoidf(ac[r][2]);
            o.w = sigmoidf(ac[r][3]);
            *(float4*)(g_g + base + (r0 + r) * CZc + cb) = o;
        }
    }
}

// ---------------------------------------------------------------------------
// Kernel 2: triangle einsum  upd[i,j,c] = sum_k a[i,k,c] * b[j,k,c]
// Tile: TI=TJ=64 (i,j), CCH=8 channels, KU=8 k-steps staged in smem.
// 512 threads; thread tile 4i x 4j x 4c (64 accumulators).
// smem layout [k][c][i] (row padded to 68) -> broadcast a-reads,
// conflict-free LDS.128 b-reads.
// ---------------------------------------------------------------------------
#define TI  64
#define KU  8
#define CCH 8
#define LDP 68

__global__ __launch_bounds__(512, 1) void k_tri()
{
    __shared__ float as[KU][CCH][LDP];
    __shared__ float bs[KU][CCH][LDP];

    const int tid = threadIdx.x;
    const int i0  = blockIdx.y * TI;
    const int j0  = blockIdx.x * TI;
    const int c0  = blockIdx.z * CCH;

    const int tc = tid & 1;          // channel half (4 channels each)
    const int tx = (tid >> 1) & 15;  // j group
    const int ty = tid >> 5;         // i group (constant within a warp)

    float acc[4][4][4];
    #pragma unroll
    for (int ii = 0; ii < 4; ++ii)
        #pragma unroll
        for (int jj = 0; jj < 4; ++jj)
            #pragma unroll
            for (int cc = 0; cc < 4; ++cc) acc[ii][jj][cc] = 0.f;

    for (int k0 = 0; k0 < NN; k0 += KU) {
        __syncthreads();
        #pragma unroll
        for (int t = tid; t < TI * KU * CCH; t += 512) {
            const int c = t & 7;
            const int u = (t >> 3) & 7;
            const int i = t >> 6;
            as[u][c][i] = g_a[((i0 + i) * NN + (k0 + u)) * CZc + c0 + c];
            bs[u][c][i] = g_b[((j0 + i) * NN + (k0 + u)) * CZc + c0 + c];
        }
        __syncthreads();

        #pragma unroll
        for (int u = 0; u < KU; ++u) {
            float af[4][4], bf[4][4];
            #pragma unroll
            for (int cc = 0; cc < 4; ++cc) {
                *(float4*)af[cc] = *(const float4*)&as[u][tc * 4 + cc][ty * 4];
                *(float4*)bf[cc] = *(const float4*)&bs[u][tc * 4 + cc][tx * 4];
            }
            #pragma unroll
            for (int ii = 0; ii < 4; ++ii)
                #pragma unroll
                for (int jj = 0; jj < 4; ++jj)
                    #pragma unroll
                    for (int cc = 0; cc < 4; ++cc)
                        acc[ii][jj][cc] += af[cc][ii] * bf[cc][jj];
        }
    }

    #pragma unroll
    for (int ii = 0; ii < 4; ++ii)
        #pragma unroll
        for (int jj = 0; jj < 4; ++jj) {
            float4 o;
            o.x = acc[ii][jj][0]; o.y = acc[ii][jj][1];
            o.z = acc[ii][jj][2]; o.w = acc[ii][jj][3];
            *(float4*)&g_upd[((i0 + ty * 4 + ii) * NN + (j0 + tx * 4 + jj)) * CZc
                             + c0 + tc * 4] = o;
        }
}

// ---------------------------------------------------------------------------
// Kernel 3: LN2(upd) @ w_out, multiplied by gate g -> out
// ---------------------------------------------------------------------------
__global__ __launch_bounds__(256, 4) void k_out(
    const float* __restrict__ gamma2,
    const float* __restrict__ beta2,
    const float* __restrict__ wout,
    float* __restrict__ out)
{
    __shared__ float us[32 * CZc];
    const int tid  = threadIdx.x;
    const int base = blockIdx.x * (32 * CZc);

    for (int t = tid; t < 32 * CZc; t += 256) us[t] = g_upd[base + t];
    __syncthreads();

    {
        const int w = tid >> 5, lane = tid & 31;
        #pragma unroll
        for (int rr = 0; rr < 4; ++rr) {
            const int row = w * 4 + rr;
            const float v0 = us[row * CZc + lane];
            const float v1 = us[row * CZc + lane + 32];
            const float v2 = us[row * CZc + lane + 64];
            const float v3 = us[row * CZc + lane + 96];
            float s  = v0 + v1 + v2 + v3;
            float s2 = v0*v0 + v1*v1 + v2*v2 + v3*v3;
            #pragma unroll
            for (int o = 16; o; o >>= 1) {
                s  += __shfl_xor_sync(0xffffffffu, s,  o);
                s2 += __shfl_xor_sync(0xffffffffu, s2, o);
            }
            const float mu   = s * (1.0f / CZc);
            const float var  = s2 * (1.0f / CZc) - mu * mu;
            const float rstd = rsqrtf(var + 1e-5f);
            us[row*CZc + lane     ] = (v0-mu)*rstd*gamma2[lane     ] + beta2[lane     ];
            us[row*CZc + lane + 32] = (v1-mu)*rstd*gamma2[lane + 32] + beta2[lane + 32];
            us[row*CZc + lane + 64] = (v2-mu)*rstd*gamma2[lane + 64] + beta2[lane + 64];
            us[row*CZc + lane + 96] = (v3-mu)*rstd*gamma2[lane + 96] + beta2[lane + 96];
        }
    }
    __syncthreads();

    const int ty = tid >> 5;
    const int tx = tid & 31;
    const int r0 = ty * 4;
    const int cb = tx * 4;

    float ac[4][4];
    #pragma unroll
    for (int r = 0; r < 4; ++r)
        #pragma unroll
        for (int c = 0; c < 4; ++c) ac[r][c] = 0.f;

    #pragma unroll 4
    for (int k = 0; k < CZc; ++k) {
        float u[4];
        #pragma unroll
        for (int r = 0; r < 4; ++r) u[r] = us[(r0 + r) * CZc + k];
        const float4 w4 = *(const float4*)(wout + k * CZc + cb);
        #pragma unroll
        for (int r = 0; r < 4; ++r) {
            ac[r][0] += u[r] * w4.x;  ac[r][1] += u[r] * w4.y;
            ac[r][2] += u[r] * w4.z;  ac[r][3] += u[r] * w4.w;
        }
    }

    #pragma unroll
    for (int r = 0; r < 4; ++r) {
        const float4 gg = *(const float4*)(g_g + base + (r0 + r) * CZc + cb);
        float4 o;
        o.x = gg.x * ac[r][0];
        o.y = gg.y * ac[r][1];
        o.z = gg.z * ac[r][2];
        o.w = gg.w * ac[r][3];
        *(float4*)(out + base + (r0 + r) * CZc + cb) = o;
    }
}

// ---------------------------------------------------------------------------
// Launch
// Input order (metadata): pair_rep, ln1_gamma, ln1_beta, w_gate_a, w_gate_b,
//                         w_a, w_b, ln2_gamma, ln2_beta, w_out, w_gate
// ---------------------------------------------------------------------------
extern "C" void kernel_launch(void* const* d_in, const int* in_sizes, int n_in,
                              void* d_out, int out_size)
{
    const float* x    = (const float*)d_in[0];
    const float* g1   = (const float*)d_in[1];
    const float* b1   = (const float*)d_in[2];
    const float* wga  = (const float*)d_in[3];
    const float* wgb  = (const float*)d_in[4];
    const float* wa   = (const float*)d_in[5];
    const float* wb   = (const float*)d_in[6];
    const float* g2   = (const float*)d_in[7];
    const float* b2   = (const float*)d_in[8];
    const float* wout = (const float*)d_in[9];
    const float* wg   = (const float*)d_in[10];

    k_proj<<<RTOT / 32, 256>>>(x, g1, b1, wga, wgb, wa, wb, wg);

    dim3 grid(NN / TI, NN / TI, CZc / CCH);
    k_tri<<<grid, 512>>>();

    k_out<<<RTOT / 32, 256>>>(g2, b2, wout, (float*)d_out);
}

// round 3
// speedup vs baseline: 1.8279x; 1.8279x over previous
#include <cuda_runtime.h>
#include <cuda_bf16.h>
#include <cstdint>

#define NN   512
#define CZc  128
#define RTOT (NN*NN)

// ---------------------------------------------------------------------------
// Scratch planes:
//   g_a[c*RTOT + i*NN + k], g_b[c*RTOT + j*NN + k], g_upd[c*RTOT + i*NN + j]
//   g_g row-major [row][c]
// ---------------------------------------------------------------------------
__device__ float g_a  [(size_t)RTOT * CZc];
__device__ float g_b  [(size_t)RTOT * CZc];
__device__ float g_g  [(size_t)RTOT * CZc];
__device__ float g_upd[(size_t)RTOT * CZc];

// ---------------------------------------------------------------------------
// Helpers (baseline-ISA only; no 'a'-gated instructions)
// ---------------------------------------------------------------------------
__device__ __forceinline__ uint32_t smem_u32(const void* p) {
    uint32_t a;
    asm("{ .reg .u64 t; cvta.to.shared.u64 t, %1; cvt.u32.u64 %0, t; }"
        : "=r"(a) : "l"(p));
    return a;
}
__device__ __forceinline__ float sigmoidf(float x) { return 1.0f / (1.0f + __expf(-x)); }

__device__ __forceinline__ void fma2(unsigned long long& d,
                                     unsigned long long a, unsigned long long b) {
    asm("fma.rn.f32x2 %0, %1, %2, %0;" : "+l"(d) : "l"(a), "l"(b));
}
__device__ __forceinline__ unsigned long long bcast2(float x) {
    unsigned long long r; unsigned xi = __float_as_uint(x);
    asm("mov.b64 %0, {%1, %1};" : "=l"(r) : "r"(xi));
    return r;
}
__device__ __forceinline__ float2 unpk2(unsigned long long v) {
    float2 o; asm("mov.b64 {%0, %1}, %2;" : "=f"(o.x), "=f"(o.y) : "l"(v)); return o;
}

__device__ __forceinline__ void ldsm4(uint32_t* r, uint32_t addr) {
    asm volatile("ldmatrix.sync.aligned.m8n8.x4.shared.b16 {%0,%1,%2,%3}, [%4];"
                 : "=r"(r[0]), "=r"(r[1]), "=r"(r[2]), "=r"(r[3]) : "r"(addr));
}
__device__ __forceinline__ void mma_bf16(float* c, const uint32_t* a, const uint32_t* b) {
    asm volatile(
        "mma.sync.aligned.m16n8k16.row.col.f32.bf16.bf16.f32 "
        "{%0,%1,%2,%3}, {%4,%5,%6,%7}, {%8,%9}, {%0,%1,%2,%3};"
        : "+f"(c[0]), "+f"(c[1]), "+f"(c[2]), "+f"(c[3])
        : "r"(a[0]), "r"(a[1]), "r"(a[2]), "r"(a[3]), "r"(b[0]), "r"(b[1]));
}

// ---------------------------------------------------------------------------
// Kernel 1: fused LN1 + 5 projections (packed f32x2 FMAs).
// a/b transposed to channel planes; g row-major.
// ---------------------------------------------------------------------------
__global__ __launch_bounds__(256, 3) void k_proj(
    const float* __restrict__ x,
    const float* __restrict__ gamma,
    const float* __restrict__ beta,
    const float* __restrict__ wga,
    const float* __restrict__ wgb,
    const float* __restrict__ wa,
    const float* __restrict__ wb,
    const float* __restrict__ wg)
{
    __shared__ float zs[32 * CZc];
    __shared__ float stage[32 * 132];

    const int tid      = threadIdx.x;
    const int base_row = blockIdx.x * 32;
    const int base_el  = base_row * CZc;

    for (int t = tid; t < 32 * CZc; t += 256) zs[t] = x[base_el + t];
    __syncthreads();

    {   // LayerNorm (8 warps x 4 rows)
        const int w = tid >> 5, lane = tid & 31;
        #pragma unroll
        for (int rr = 0; rr < 4; ++rr) {
            const int row = w * 4 + rr;
            const float v0 = zs[row*CZc + lane];
            const float v1 = zs[row*CZc + lane + 32];
            const float v2 = zs[row*CZc + lane + 64];
            const float v3 = zs[row*CZc + lane + 96];
            float s  = v0 + v1 + v2 + v3;
            float s2 = v0*v0 + v1*v1 + v2*v2 + v3*v3;
            #pragma unroll
            for (int o = 16; o; o >>= 1) {
                s  += __shfl_xor_sync(0xffffffffu, s,  o);
                s2 += __shfl_xor_sync(0xffffffffu, s2, o);
            }
            const float mu   = s * (1.0f / CZc);
            const float var  = s2 * (1.0f / CZc) - mu * mu;
            const float rstd = rsqrtf(var + 1e-5f);
            zs[row*CZc + lane     ] = (v0-mu)*rstd*gamma[lane     ] + beta[lane     ];
            zs[row*CZc + lane + 32] = (v1-mu)*rstd*gamma[lane + 32] + beta[lane + 32];
            zs[row*CZc + lane + 64] = (v2-mu)*rstd*gamma[lane + 64] + beta[lane + 64];
            zs[row*CZc + lane + 96] = (v3-mu)*rstd*gamma[lane + 96] + beta[lane + 96];
        }
    }
    __syncthreads();

    const int ty = tid >> 5, tx = tid & 31;
    const int r0 = ty * 4,  cb = tx * 4;

    for (int pass = 0; pass < 2; ++pass) {
        const float* __restrict__ Wg = pass ? wgb : wga;
        const float* __restrict__ Wl = pass ? wb  : wa;
        float* __restrict__ Out      = pass ? g_b : g_a;

        unsigned long long ag[4][2], al[4][2];
        #pragma unroll
        for (int r = 0; r < 4; ++r) { ag[r][0]=0; ag[r][1]=0; al[r][0]=0; al[r][1]=0; }

        #pragma unroll 2
        for (int k = 0; k < CZc; ++k) {
            unsigned long long zz[4];
            #pragma unroll
            for (int r = 0; r < 4; ++r) zz[r] = bcast2(zs[(r0 + r)*CZc + k]);
            const ulonglong2 wg2 = *(const ulonglong2*)(Wg + k*CZc + cb);
            const ulonglong2 wl2 = *(const ulonglong2*)(Wl + k*CZc + cb);
            #pragma unroll
            for (int r = 0; r < 4; ++r) {
                fma2(ag[r][0], zz[r], wg2.x); fma2(ag[r][1], zz[r], wg2.y);
                fma2(al[r][0], zz[r], wl2.x); fma2(al[r][1], zz[r], wl2.y);
            }
        }
        #pragma unroll
        for (int r = 0; r < 4; ++r) {
            const float2 ga = unpk2(ag[r][0]), gb = unpk2(ag[r][1]);
            const float2 la = unpk2(al[r][0]), lb = unpk2(al[r][1]);
            float4 o;
            o.x = sigmoidf(ga.x)*la.x;  o.y = sigmoidf(ga.y)*la.y;
            o.z = sigmoidf(gb.x)*lb.x;  o.w = sigmoidf(gb.y)*lb.y;
            *(float4*)&stage[(r0 + r)*132 + cb] = o;
        }
        __syncthreads();
        {   // coalesced transposed store
            const int c = tid >> 1, half = tid & 1;
            float* dst = Out + (size_t)c * RTOT + base_row + half * 16;
            #pragma unroll
            for (int q = 0; q < 4; ++q) {
                const int rr = half*16 + q*4;
                float4 v;
                v.x = stage[(rr+0)*132 + c];
                v.y = stage[(rr+1)*132 + c];
                v.z = stage[(rr+2)*132 + c];
                v.w = stage[(rr+3)*132 + c];
                *(float4*)(dst + q*4) = v;
            }
        }
        __syncthreads();
    }

    {   // gate: sigmoid(z @ w_gate) -> g_g (row-major)
        unsigned long long ac[4][2];
        #pragma unroll
        for (int r = 0; r < 4; ++r) { ac[r][0]=0; ac[r][1]=0; }
        #pragma unroll 2
        for (int k = 0; k < CZc; ++k) {
            unsigned long long zz[4];
            #pragma unroll
            for (int r = 0; r < 4; ++r) zz[r] = bcast2(zs[(r0 + r)*CZc + k]);
            const ulonglong2 w2 = *(const ulonglong2*)(wg + k*CZc + cb);
            #pragma unroll
            for (int r = 0; r < 4; ++r) {
                fma2(ac[r][0], zz[r], w2.x); fma2(ac[r][1], zz[r], w2.y);
            }
        }
        #pragma unroll
        for (int r = 0; r < 4; ++r) {
            const float2 a0 = unpk2(ac[r][0]), a1 = unpk2(ac[r][1]);
            float4 o;
            o.x = sigmoidf(a0.x); o.y = sigmoidf(a0.y);
            o.z = sigmoidf(a1.x); o.w = sigmoidf(a1.y);
            *(float4*)(g_g + base_el + (r0 + r)*CZc + cb) = o;
        }
    }
}

// ---------------------------------------------------------------------------
// Kernel 2: triangle einsum via mma.sync bf16 hi/lo split (3 products).
// CTA: channel plane c, 128x128 (i,j) tile, K in 16 chunks of 32.
// smem rows padded to 40 halves (80B) -> conflict-free ldmatrix.
// 8 warps in 4(i) x 2(j): each warp 32(i) x 64(j).
// ---------------------------------------------------------------------------
__global__ __launch_bounds__(256, 2) void k_tri_mma()
{
    __shared__ __align__(16) __nv_bfloat16 sh[4][128][40];  // Ah, Al, Bh, Bl

    const int tid  = threadIdx.x;
    const int wid  = tid >> 5;
    const int lane = tid & 31;
    const int c    = blockIdx.z;
    const int i0   = blockIdx.y * 128;
    const int j0   = blockIdx.x * 128;

    const float* Ap = g_a + (size_t)c * RTOT + (size_t)i0 * NN;
    const float* Bp = g_b + (size_t)c * RTOT + (size_t)j0 * NN;

    const int wi = wid & 3, wj = wid >> 2;
    const int ib = wi * 32, jb = wj * 64;

    float acc[2][8][4];
    #pragma unroll
    for (int m = 0; m < 2; ++m)
        #pragma unroll
        for (int q = 0; q < 8; ++q)
            #pragma unroll
            for (int e = 0; e < 4; ++e) acc[m][q][e] = 0.f;

    const int frow = tid >> 1;          // 0..127
    const int fk   = (tid & 1) * 16;    // 0 / 16

    const uint32_t sbase = smem_u32(&sh[0][0][0]);
    const int lrow = lane & 15;
    const int lcolb = ((lane >> 4) & 1) * 16;

    for (int ch = 0; ch < 16; ++ch) {
        const int k0 = ch * 32;

        // ---- fill: fp32 load, hi/lo bf16 split, store to smem ----
        float xa[16], xb[16];
        #pragma unroll
        for (int q = 0; q < 4; ++q)
            *(float4*)&xa[q*4] = *(const float4*)(Ap + (size_t)frow*NN + k0 + fk + q*4);
        #pragma unroll
        for (int q = 0; q < 4; ++q)
            *(float4*)&xb[q*4] = *(const float4*)(Bp + (size_t)frow*NN + k0 + fk + q*4);

        uint32_t ah[8], al[8], bh[8], bl[8];
        #pragma unroll
        for (int p = 0; p < 8; ++p) {
            const float a0 = xa[2*p], a1 = xa[2*p+1];
            const __nv_bfloat16 h0 = __float2bfloat16_rn(a0);
            const __nv_bfloat16 h1 = __float2bfloat16_rn(a1);
            const float l0 = a0 - __bfloat162float(h0);
            const float l1 = a1 - __bfloat162float(h1);
            const __nv_bfloat16 g0 = __float2bfloat16_rn(l0);
            const __nv_bfloat16 g1 = __float2bfloat16_rn(l1);
            ah[p] = (uint32_t)__bfloat16_as_ushort(h0) | ((uint32_t)__bfloat16_as_ushort(h1) << 16);
            al[p] = (uint32_t)__bfloat16_as_ushort(g0) | ((uint32_t)__bfloat16_as_ushort(g1) << 16);

            const float b0 = xb[2*p], b1 = xb[2*p+1];
            const __nv_bfloat16 k0h = __float2bfloat16_rn(b0);
            const __nv_bfloat16 k1h = __float2bfloat16_rn(b1);
            const float m0 = b0 - __bfloat162float(k0h);
            const float m1 = b1 - __bfloat162float(k1h);
            const __nv_bfloat16 n0 = __float2bfloat16_rn(m0);
            const __nv_bfloat16 n1 = __float2bfloat16_rn(m1);
            bh[p] = (uint32_t)__bfloat16_as_ushort(k0h) | ((uint32_t)__bfloat16_as_ushort(k1h) << 16);
            bl[p] = (uint32_t)__bfloat16_as_ushort(n0) | ((uint32_t)__bfloat16_as_ushort(n1) << 16);
        }
        *(uint4*)&sh[0][frow][fk]     = make_uint4(ah[0], ah[1], ah[2], ah[3]);
        *(uint4*)&sh[0][frow][fk + 8] = make_uint4(ah[4], ah[5], ah[6], ah[7]);
        *(uint4*)&sh[1][frow][fk]     = make_uint4(al[0], al[1], al[2], al[3]);
        *(uint4*)&sh[1][frow][fk + 8] = make_uint4(al[4], al[5], al[6], al[7]);
        *(uint4*)&sh[2][frow][fk]     = make_uint4(bh[0], bh[1], bh[2], bh[3]);
        *(uint4*)&sh[2][frow][fk + 8] = make_uint4(bh[4], bh[5], bh[6], bh[7]);
        *(uint4*)&sh[3][frow][fk]     = make_uint4(bl[0], bl[1], bl[2], bl[3]);
        *(uint4*)&sh[3][frow][fk + 8] = make_uint4(bl[4], bl[5], bl[6], bl[7]);
        __syncthreads();

        // ---- compute: 2 k16 steps ----
        #pragma unroll
        for (int s16 = 0; s16 < 2; ++s16) {
            const uint32_t colb = (uint32_t)(s16 * 32 + lcolb);

            uint32_t Bh[4][4], Bl[4][4];
            #pragma unroll
            for (int p = 0; p < 4; ++p) {
                const uint32_t r = (uint32_t)(jb + p*16 + lrow);
                ldsm4(Bh[p], sbase + 2u*10240u + r*80u + colb);
                ldsm4(Bl[p], sbase + 3u*10240u + r*80u + colb);
            }
            #pragma unroll
            for (int m = 0; m < 2; ++m) {
                uint32_t Ah[4], Al[4];
                const uint32_t r = (uint32_t)(ib + m*16 + lrow);
                ldsm4(Ah, sbase +            r*80u + colb);
                ldsm4(Al, sbase + 10240u   + r*80u + colb);
                #pragma unroll
                for (int q = 0; q < 8; ++q) {
                    const int p = q >> 1, o = q & 1;
                    uint32_t vh[2] = { Bh[p][o], Bh[p][o + 2] };
                    uint32_t vl[2] = { Bl[p][o], Bl[p][o + 2] };
                    mma_bf16(acc[m][q], Ah, vh);
                    mma_bf16(acc[m][q], Ah, vl);
                    mma_bf16(acc[m][q], Al, vh);
                }
            }
        }
        __syncthreads();
    }

    // ---- epilogue: acc -> g_upd plane ----
    {
        const int g  = lane >> 2;
        const int tg = lane & 3;
        float* plane = g_upd + (size_t)c * RTOT;
        #pragma unroll
        for (int m = 0; m < 2; ++m) {
            const int irow = i0 + ib + m*16 + g;
            #pragma unroll
            for (int q = 0; q < 8; ++q) {
                const int jcol = j0 + jb + q*8 + tg*2;
                float2 v0; v0.x = acc[m][q][0]; v0.y = acc[m][q][1];
                float2 v1; v1.x = acc[m][q][2]; v1.y = acc[m][q][3];
                *(float2*)(plane + (size_t)irow      * NN + jcol) = v0;
                *(float2*)(plane + (size_t)(irow + 8)* NN + jcol) = v1;
            }
        }
    }
}

// ---------------------------------------------------------------------------
// Kernel 3: LN2(upd) @ w_out * gate -> out (plane reads, smem transpose).
// ---------------------------------------------------------------------------
__global__ __launch_bounds__(256, 3) void k_out(
    const float* __restrict__ gamma2,
    const float* __restrict__ beta2,
    const float* __restrict__ wout,
    float* __restrict__ out)
{
    __shared__ float us[128 * 36];
    __shared__ float ln[32 * 132];

    const int tid  = threadIdx.x;
    const int base = blockIdx.x * 32;

    {
        const int c = tid >> 1, half = tid & 1;
        const float* src = g_upd + (size_t)c * RTOT + base + half * 16;
        #pragma unroll
        for (int q = 0; q < 4; ++q) {
            const float4 v = *(const float4*)(src + q * 4);
            *(float4*)&us[c * 36 + half * 16 + q * 4] = v;
        }
    }
    __syncthreads();

    {
        const int w = tid >> 5, lane = tid & 31;
        #pragma unroll
        for (int jj = 0; jj < 4; ++jj) {
            const int j = w * 4 + jj;
            const float v0 = us[(lane      ) * 36 + j];
            const float v1 = us[(lane + 32 ) * 36 + j];
            const float v2 = us[(lane + 64 ) * 36 + j];
            const float v3 = us[(lane + 96 ) * 36 + j];
            float s  = v0 + v1 + v2 + v3;
            float s2 = v0*v0 + v1*v1 + v2*v2 + v3*v3;
            #pragma unroll
            for (int o = 16; o; o >>= 1) {
                s  += __shfl_xor_sync(0xffffffffu, s,  o);
                s2 += __shfl_xor_sync(0xffffffffu, s2, o);
            }
            const float mu   = s * (1.0f / CZc);
            const float var  = s2 * (1.0f / CZc) - mu * mu;
            const float rstd = rsqrtf(var + 1e-5f);
            ln[j*132 + lane     ] = (v0-mu)*rstd*gamma2[lane     ] + beta2[lane     ];
            ln[j*132 + lane + 32] = (v1-mu)*rstd*gamma2[lane + 32] + beta2[lane + 32];
            ln[j*132 + lane + 64] = (v2-mu)*rstd*gamma2[lane + 64] + beta2[lane + 64];
            ln[j*132 + lane + 96] = (v3-mu)*rstd*gamma2[lane + 96] + beta2[lane + 96];
        }
    }
    __syncthreads();

    const int ty = tid >> 5, tx = tid & 31;
    const int r0 = ty * 4,  cb = tx * 4;

    unsigned long long ac[4][2];
    #pragma unroll
    for (int r = 0; r < 4; ++r) { ac[r][0]=0; ac[r][1]=0; }

    #pragma unroll 2
    for (int k = 0; k < CZc; ++k) {
        unsigned long long zz[4];
        #pragma unroll
        for (int r = 0; r < 4; ++r) zz[r] = bcast2(ln[(r0 + r)*132 + k]);
        const ulonglong2 w2 = *(const ulonglong2*)(wout + k*CZc + cb);
        #pragma unroll
        for (int r = 0; r < 4; ++r) {
            fma2(ac[r][0], zz[r], w2.x); fma2(ac[r][1], zz[r], w2.y);
        }
    }

    #pragma unroll
    for (int r = 0; r < 4; ++r) {
        const float2 a0 = unpk2(ac[r][0]), a1 = unpk2(ac[r][1]);
        const float4 gg = *(const float4*)(g_g + (size_t)(base + r0 + r)*CZc + cb);
        float4 o;
        o.x = gg.x * a0.x;  o.y = gg.y * a0.y;
        o.z = gg.z * a1.x;  o.w = gg.w * a1.y;
        *(float4*)(out + (size_t)(base + r0 + r)*CZc + cb) = o;
    }
}

// ---------------------------------------------------------------------------
// Launch
// ---------------------------------------------------------------------------
extern "C" void kernel_launch(void* const* d_in, const int* in_sizes, int n_in,
                              void* d_out, int out_size)
{
    const float* x    = (const float*)d_in[0];
    const float* g1   = (const float*)d_in[1];
    const float* b1   = (const float*)d_in[2];
    const float* wga  = (const float*)d_in[3];
    const float* wgb  = (const float*)d_in[4];
    const float* wa   = (const float*)d_in[5];
    const float* wb   = (const float*)d_in[6];
    const float* g2   = (const float*)d_in[7];
    const float* b2   = (const float*)d_in[8];
    const float* wout = (const float*)d_in[9];
    const float* wg   = (const float*)d_in[10];

    k_proj<<<RTOT / 32, 256>>>(x, g1, b1, wga, wgb, wa, wb, wg);

    dim3 grid(NN / 128, NN / 128, CZc);
    k_tri_mma<<<grid, 256>>>();

    k_out<<<RTOT / 32, 256>>>(g2, b2, wout, (float*)d_out);
}

// round 4
// speedup vs baseline: 1.8408x; 1.0070x over previous
#include <cuda_runtime.h>
#include <cuda_bf16.h>
#include <cstdint>

#define NN   512
#define CZc  128
#define RTOT (NN*NN)

// ---------------------------------------------------------------------------
// Scratch planes (device globals; allocations forbidden).
// a/b as bf16 hi/lo channel planes: g_ah[c*RTOT + row*?]. Row space is the
// flat 262144-row space; per plane c: matrix [i][k] (a) / [j][k] (b).
// g_upd fp32 planes [c][i][j]; g_g fp32 row-major [row][c].
// ---------------------------------------------------------------------------
__device__ __nv_bfloat16 g_ah[(size_t)RTOT * CZc];
__device__ __nv_bfloat16 g_al[(size_t)RTOT * CZc];
__device__ __nv_bfloat16 g_bh[(size_t)RTOT * CZc];
__device__ __nv_bfloat16 g_bl[(size_t)RTOT * CZc];
__device__ float g_g  [(size_t)RTOT * CZc];
__device__ float g_upd[(size_t)RTOT * CZc];

// ---------------------------------------------------------------------------
// Helpers (baseline ISA only)
// ---------------------------------------------------------------------------
__device__ __forceinline__ uint32_t smem_u32(const void* p) {
    uint32_t a;
    asm("{ .reg .u64 t; cvta.to.shared.u64 t, %1; cvt.u32.u64 %0, t; }"
        : "=r"(a) : "l"(p));
    return a;
}
__device__ __forceinline__ float sigmoidf(float x) { return 1.0f / (1.0f + __expf(-x)); }

__device__ __forceinline__ void ldsm4(uint32_t* r, uint32_t addr) {
    asm volatile("ldmatrix.sync.aligned.m8n8.x4.shared.b16 {%0,%1,%2,%3}, [%4];"
                 : "=r"(r[0]), "=r"(r[1]), "=r"(r[2]), "=r"(r[3]) : "r"(addr));
}
__device__ __forceinline__ void mma_bf16(float* c, const uint32_t* a, const uint32_t* b) {
    asm volatile(
        "mma.sync.aligned.m16n8k16.row.col.f32.bf16.bf16.f32 "
        "{%0,%1,%2,%3}, {%4,%5,%6,%7}, {%8,%9}, {%0,%1,%2,%3};"
        : "+f"(c[0]), "+f"(c[1]), "+f"(c[2]), "+f"(c[3])
        : "r"(a[0]), "r"(a[1]), "r"(a[2]), "r"(a[3]), "r"(b[0]), "r"(b[1]));
}
__device__ __forceinline__ void cp16(uint32_t dst, const void* src) {
    asm volatile("cp.async.cg.shared.global [%0], [%1], 16;"
                 :: "r"(dst), "l"(src) : "memory");
}
#define CP_COMMIT() asm volatile("cp.async.commit_group;" ::: "memory")
#define CP_WAIT0()  asm volatile("cp.async.wait_group 0;"  ::: "memory")

// 128x128x128 bf16 hi/lo split mma: A [row][k], B [n][k], both 136-half rows
// (272B stride). 8 warps as 4(m) x 2(n): warp tile 32 x 64. Zeroes acc.
__device__ __forceinline__ void mma_tile_k128(
    float (*acc)[8][4],
    uint32_t a_h, uint32_t a_l, uint32_t b_h, uint32_t b_l,
    int ib, int jb, int lane)
{
    const int lrow = lane & 15;
    const uint32_t lcolb = (uint32_t)((lane >> 4) & 1) * 16u;

    #pragma unroll
    for (int m = 0; m < 2; ++m)
        #pragma unroll
        for (int q = 0; q < 8; ++q)
            #pragma unroll
            for (int e = 0; e < 4; ++e) acc[m][q][e] = 0.f;

    #pragma unroll
    for (int s = 0; s < 8; ++s) {
        const uint32_t colb = (uint32_t)s * 32u + lcolb;
        uint32_t Bh[4][4], Bl[4][4];
        #pragma unroll
        for (int p = 0; p < 4; ++p) {
            const uint32_t r = (uint32_t)(jb + p*16 + lrow);
            ldsm4(Bh[p], b_h + r*272u + colb);
            ldsm4(Bl[p], b_l + r*272u + colb);
        }
        #pragma unroll
        for (int m = 0; m < 2; ++m) {
            uint32_t Ah[4], Al[4];
            const uint32_t r = (uint32_t)(ib + m*16 + lrow);
            ldsm4(Ah, a_h + r*272u + colb);
            ldsm4(Al, a_l + r*272u + colb);
            #pragma unroll
            for (int q = 0; q < 8; ++q) {
                const int p = q >> 1, o = q & 1;
                uint32_t vh[2] = { Bh[p][o], Bh[p][o + 2] };
                uint32_t vl[2] = { Bl[p][o], Bl[p][o + 2] };
                mma_bf16(acc[m][q], Ah, vh);
                mma_bf16(acc[m][q], Ah, vl);
                mma_bf16(acc[m][q], Al, vh);
            }
        }
    }
}

// Load weight W [k][n] (128x128 fp32, row-major) transposed into
// wh/wl [n][136-half rows] as bf16 hi/lo.
__device__ __forceinline__ void load_w_t(const float* __restrict__ W,
                                         __nv_bfloat16* wh, __nv_bfloat16* wl,
                                         int tid)
{
    #pragma unroll
    for (int e = 0; e < 16; ++e) {
        const int idx = e * 256 + tid;
        const int k = idx >> 5, n4 = (idx & 31) * 4;
        const float4 v = *(const float4*)(W + k * 128 + n4);
        #pragma unroll
        for (int j = 0; j < 4; ++j) {
            const float vv = j == 0 ? v.x : j == 1 ? v.y : j == 2 ? v.z : v.w;
            const __nv_bfloat16 h = __float2bfloat16_rn(vv);
            wh[(n4 + j) * 136 + k] = h;
            wl[(n4 + j) * 136 + k] = __float2bfloat16_rn(vv - __bfloat162float(h));
        }
    }
}

// ---------------------------------------------------------------------------
// Kernel 1: LN1 + all 5 projections on tensor pipe.
// Dyn smem: region1 = zh/zl (69632 B), region2 = x | (wh/wl) | (stage h/l).
// ---------------------------------------------------------------------------
__global__ __launch_bounds__(256, 1) void k_proj(
    const float* __restrict__ x,
    const float* __restrict__ gamma,
    const float* __restrict__ beta,
    const float* __restrict__ wga,
    const float* __restrict__ wgb,
    const float* __restrict__ wa,
    const float* __restrict__ wb,
    const float* __restrict__ wg)
{
    extern __shared__ char sraw[];
    __nv_bfloat16* zh = (__nv_bfloat16*)sraw;            // [128][136]
    __nv_bfloat16* zl = zh + 128 * 136;
    float*         xs = (float*)(sraw + 69632);          // [128][136]
    __nv_bfloat16* wh = (__nv_bfloat16*)(sraw + 69632);  // [128][136]
    __nv_bfloat16* wl = wh + 128 * 136;

    const int tid  = threadIdx.x;
    const int lane = tid & 31, wid = tid >> 5;
    const int r0   = blockIdx.x * 128;

    // load x tile
    #pragma unroll
    for (int e = 0; e < 16; ++e) {
        const int idx = e * 256 + tid;
        const int r = idx >> 5, c4 = (idx & 31) * 4;
        *(float4*)&xs[r * 136 + c4] = *(const float4*)(x + (size_t)(r0 + r) * CZc + c4);
    }
    __syncthreads();

    // LN: warp handles 16 rows; write z as bf16 hi/lo
    {
        const float ga0 = gamma[lane],      ga1 = gamma[lane + 32];
        const float ga2 = gamma[lane + 64], ga3 = gamma[lane + 96];
        const float be0 = beta[lane],       be1 = beta[lane + 32];
        const float be2 = beta[lane + 64],  be3 = beta[lane + 96];
        for (int rr = 0; rr < 16; ++rr) {
            const int r = wid * 16 + rr;
            const float v0 = xs[r*136 + lane];
            const float v1 = xs[r*136 + lane + 32];
            const float v2 = xs[r*136 + lane + 64];
            const float v3 = xs[r*136 + lane + 96];
            float s  = v0 + v1 + v2 + v3;
            float s2 = v0*v0 + v1*v1 + v2*v2 + v3*v3;
            #pragma unroll
            for (int o = 16; o; o >>= 1) {
                s  += __shfl_xor_sync(0xffffffffu, s,  o);
                s2 += __shfl_xor_sync(0xffffffffu, s2, o);
            }
            const float mu   = s * (1.0f / CZc);
            const float var  = s2 * (1.0f / CZc) - mu * mu;
            const float rstd = rsqrtf(var + 1e-5f);
            const float z0 = (v0-mu)*rstd*ga0 + be0;
            const float z1 = (v1-mu)*rstd*ga1 + be1;
            const float z2 = (v2-mu)*rstd*ga2 + be2;
            const float z3 = (v3-mu)*rstd*ga3 + be3;
            #pragma unroll
            for (int j = 0; j < 4; ++j) {
                const float zv = j==0?z0:j==1?z1:j==2?z2:z3;
                const int c = lane + j*32;
                const __nv_bfloat16 h = __float2bfloat16_rn(zv);
                zh[r*136 + c] = h;
                zl[r*136 + c] = __float2bfloat16_rn(zv - __bfloat162float(h));
            }
        }
    }

    const int wi = wid & 3, wj = wid >> 2;
    const int ib = wi * 32, jb = wj * 64;
    const int g = lane >> 2, tg = lane & 3;
    const uint32_t zhb = smem_u32(zh), zlb = smem_u32(zl);
    const uint32_t whb = smem_u32(wh), wlb = smem_u32(wl);

    float accG[2][8][4], accL[2][8][4];

    // passes A and B: out = sigmoid(z@Wg) * (z@Wl) -> bf16 hi/lo planes
    for (int pass = 0; pass < 2; ++pass) {
        const float* Wg_ = pass ? wgb : wga;
        const float* Wl_ = pass ? wb  : wa;
        __nv_bfloat16* outh = pass ? g_bh : g_ah;
        __nv_bfloat16* outl = pass ? g_bl : g_al;

        __syncthreads();
        load_w_t(Wg_, wh, wl, tid);
        __syncthreads();
        mma_tile_k128(accG, zhb, zlb, whb, wlb, ib, jb, lane);
        __syncthreads();
        load_w_t(Wl_, wh, wl, tid);
        __syncthreads();
        mma_tile_k128(accL, zhb, zlb, whb, wlb, ib, jb, lane);
        __syncthreads();

        // combine + stage transposed [c][i] into w region
        #pragma unroll
        for (int m = 0; m < 2; ++m)
            #pragma unroll
            for (int q = 0; q < 8; ++q) {
                const int cbase = jb + q*8 + tg*2;
                const int ibase = ib + m*16 + g;
                #pragma unroll
                for (int e = 0; e < 4; ++e) {
                    const int c  = cbase + (e & 1);
                    const int ii = ibase + 8 * (e >> 1);
                    const float v = sigmoidf(accG[m][q][e]) * accL[m][q][e];
                    const __nv_bfloat16 h = __float2bfloat16_rn(v);
                    wh[c*136 + ii] = h;
                    wl[c*136 + ii] = __float2bfloat16_rn(v - __bfloat162float(h));
                }
            }
        __syncthreads();
        // coalesced plane stores
        {
            const int c = tid >> 1, half = tid & 1;
            __nv_bfloat16* dh = outh + (size_t)c * RTOT + r0 + half*64;
            __nv_bfloat16* dl = outl + (size_t)c * RTOT + r0 + half*64;
            #pragma unroll
            for (int bq = 0; bq < 8; ++bq) {
                *(uint4*)(dh + bq*8) = *(const uint4*)&wh[c*136 + half*64 + bq*8];
                *(uint4*)(dl + bq*8) = *(const uint4*)&wl[c*136 + half*64 + bq*8];
            }
        }
    }

    // gate pass: sigmoid(z @ w_gate) -> g_g row-major fp32
    __syncthreads();
    load_w_t(wg, wh, wl, tid);
    __syncthreads();
    mma_tile_k128(accG, zhb, zlb, whb, wlb, ib, jb, lane);

    #pragma unroll
    for (int m = 0; m < 2; ++m)
        #pragma unroll
        for (int q = 0; q < 8; ++q) {
            const int cc = jb + q*8 + tg*2;
            const size_t i1 = (size_t)(r0 + ib + m*16 + g);
            float2 v0, v1;
            v0.x = sigmoidf(accG[m][q][0]); v0.y = sigmoidf(accG[m][q][1]);
            v1.x = sigmoidf(accG[m][q][2]); v1.y = sigmoidf(accG[m][q][3]);
            *(float2*)(g_g + i1*CZc + cc)       = v0;
            *(float2*)(g_g + (i1 + 8)*CZc + cc) = v1;
        }
}

// ---------------------------------------------------------------------------
// Kernel 2: triangle einsum. Pure-copy fill via cp.async (planes already
// bf16 hi/lo), K chunks of 64, smem [4][128][72] halves.
// ---------------------------------------------------------------------------
__global__ __launch_bounds__(256, 2) void k_tri()
{
    extern __shared__ char sraw[];
    const uint32_t sb = smem_u32(sraw);

    const int tid  = threadIdx.x;
    const int lane = tid & 31, wid = tid >> 5;
    const int c  = blockIdx.z;
    const int i0 = blockIdx.y * 128;
    const int j0 = blockIdx.x * 128;
    const int wi = wid & 3, wj = wid >> 2;
    const int ib = wi * 32, jb = wj * 64;
    const int lrow = lane & 15;
    const uint32_t lcolb = (uint32_t)((lane >> 4) & 1) * 16u;

    const __nv_bfloat16* bases[4] = {
        g_ah + (size_t)c * RTOT + (size_t)i0 * NN,
        g_al + (size_t)c * RTOT + (size_t)i0 * NN,
        g_bh + (size_t)c * RTOT + (size_t)j0 * NN,
        g_bl + (size_t)c * RTOT + (size_t)j0 * NN };

    float acc[2][8][4];
    #pragma unroll
    for (int m = 0; m < 2; ++m)
        #pragma unroll
        for (int q = 0; q < 8; ++q)
            #pragma unroll
            for (int e = 0; e < 4; ++e) acc[m][q][e] = 0.f;

    const int seg = tid & 7;
    for (int ch = 0; ch < 8; ++ch) {
        const int k0 = ch * 64;
        __syncthreads();
        #pragma unroll
        for (int e = 0; e < 16; ++e) {
            const int arr = e >> 2;
            const int row = ((e & 3) * 256 + tid) >> 3;
            cp16(sb + (uint32_t)(arr * 18432 + row * 144 + seg * 16),
                 bases[arr] + (size_t)row * NN + k0 + seg * 8);
        }
        CP_COMMIT();
        CP_WAIT0();
        __syncthreads();

        #pragma unroll
        for (int s = 0; s < 4; ++s) {
            const uint32_t colb = (uint32_t)s * 32u + lcolb;
            uint32_t Bh[4][4], Bl[4][4];
            #pragma unroll
            for (int p = 0; p < 4; ++p) {
                const uint32_t r = (uint32_t)(jb + p*16 + lrow);
                ldsm4(Bh[p], sb + 2u*18432u + r*144u + colb);
                ldsm4(Bl[p], sb + 3u*18432u + r*144u + colb);
            }
            #pragma unroll
            for (int m = 0; m < 2; ++m) {
                uint32_t Ah[4], Al[4];
                const uint32_t r = (uint32_t)(ib + m*16 + lrow);
                ldsm4(Ah, sb +           r*144u + colb);
                ldsm4(Al, sb + 18432u +  r*144u + colb);
                #pragma unroll
                for (int q = 0; q < 8; ++q) {
                    const int p = q >> 1, o = q & 1;
                    uint32_t vh[2] = { Bh[p][o], Bh[p][o + 2] };
                    uint32_t vl[2] = { Bl[p][o], Bl[p][o + 2] };
                    mma_bf16(acc[m][q], Ah, vh);
                    mma_bf16(acc[m][q], Ah, vl);
                    mma_bf16(acc[m][q], Al, vh);
                }
            }
        }
    }

    // epilogue -> g_upd fp32 plane
    {
        const int g = lane >> 2, tg = lane & 3;
        float* plane = g_upd + (size_t)c * RTOT;
        #pragma unroll
        for (int m = 0; m < 2; ++m) {
            const int irow = i0 + ib + m*16 + g;
            #pragma unroll
            for (int q = 0; q < 8; ++q) {
                const int jcol = j0 + jb + q*8 + tg*2;
                float2 v0; v0.x = acc[m][q][0]; v0.y = acc[m][q][1];
                float2 v1; v1.x = acc[m][q][2]; v1.y = acc[m][q][3];
                *(float2*)(plane + (size_t)irow       * NN + jcol) = v0;
                *(float2*)(plane + (size_t)(irow + 8) * NN + jcol) = v1;
            }
        }
    }
}

// ---------------------------------------------------------------------------
// Kernel 3: LN2(upd) @ w_out * gate -> out, on tensor pipe.
// Dyn smem: region1 = z2 hi/lo (69632), region2 = us fp32 | wh/wl.
// ---------------------------------------------------------------------------
__global__ __launch_bounds__(256, 1) void k_out(
    const float* __restrict__ gamma2,
    const float* __restrict__ beta2,
    const float* __restrict__ wout,
    float* __restrict__ out)
{
    extern __shared__ char sraw[];
    __nv_bfloat16* zh = (__nv_bfloat16*)sraw;            // [row][136]
    __nv_bfloat16* zl = zh + 128 * 136;
    float*         us = (float*)(sraw + 69632);          // [c][136]
    __nv_bfloat16* wh = (__nv_bfloat16*)(sraw + 69632);
    __nv_bfloat16* wl = wh + 128 * 136;
    __shared__ float sgb[256];

    const int tid  = threadIdx.x;
    const int lane = tid & 31, wid = tid >> 5;
    const int r0   = blockIdx.x * 128;

    if (tid < 128) sgb[tid] = gamma2[tid];
    else           sgb[tid] = beta2[tid - 128];

    // load upd tile from planes: us[c][r]
    #pragma unroll
    for (int e = 0; e < 16; ++e) {
        const int idx = e * 256 + tid;
        const int cc = idx >> 5, r4 = (idx & 31) * 4;
        *(float4*)&us[cc * 136 + r4] =
            *(const float4*)(g_upd + (size_t)cc * RTOT + r0 + r4);
    }
    __syncthreads();

    // LN over c per row (2 threads per row), write z2 hi/lo [row][c]
    {
        const int r = tid >> 1, h = tid & 1;
        float s = 0.f, s2 = 0.f;
        #pragma unroll 8
        for (int ccq = 0; ccq < 64; ++ccq) {
            const float v = us[(h*64 + ccq) * 136 + r];
            s += v; s2 += v * v;
        }
        s  += __shfl_xor_sync(0xffffffffu, s,  1);
        s2 += __shfl_xor_sync(0xffffffffu, s2, 1);
        const float mu   = s * (1.0f / CZc);
        const float var  = s2 * (1.0f / CZc) - mu * mu;
        const float rstd = rsqrtf(var + 1e-5f);
        #pragma unroll 8
        for (int ccq = 0; ccq < 64; ++ccq) {
            const int c = h*64 + ccq;
            const float v = us[c * 136 + r];
            const float z = (v - mu) * rstd * sgb[c] + sgb[128 + c];
            const __nv_bfloat16 hh = __float2bfloat16_rn(z);
            zh[r*136 + c] = hh;
            zl[r*136 + c] = __float2bfloat16_rn(z - __bfloat162float(hh));
        }
    }
    __syncthreads();

    load_w_t(wout, wh, wl, tid);
    __syncthreads();

    const int wi = wid & 3, wj = wid >> 2;
    const int ib = wi * 32, jb = wj * 64;
    float acc[2][8][4];
    mma_tile_k128(acc, smem_u32(zh), smem_u32(zl), smem_u32(wh), smem_u32(wl),
                  ib, jb, lane);

    // epilogue: multiply gate, store fp32 row-major
    {
        const int g = lane >> 2, tg = lane & 3;
        #pragma unroll
        for (int m = 0; m < 2; ++m)
            #pragma unroll
            for (int q = 0; q < 8; ++q) {
                const int cc = jb + q*8 + tg*2;
                const size_t i1 = (size_t)(r0 + ib + m*16 + g);
                const float2 gg0 = *(const float2*)(g_g + i1*CZc + cc);
                const float2 gg1 = *(const float2*)(g_g + (i1 + 8)*CZc + cc);
                float2 v0, v1;
                v0.x = gg0.x * acc[m][q][0]; v0.y = gg0.y * acc[m][q][1];
                v1.x = gg1.x * acc[m][q][2]; v1.y = gg1.y * acc[m][q][3];
                *(float2*)(out + i1*CZc + cc)       = v0;
                *(float2*)(out + (i1 + 8)*CZc + cc) = v1;
            }
    }
}

// ---------------------------------------------------------------------------
// Launch
// ---------------------------------------------------------------------------
extern "C" void kernel_launch(void* const* d_in, const int* in_sizes, int n_in,
                              void* d_out, int out_size)
{
    const float* x    = (const float*)d_in[0];
    const float* g1   = (const float*)d_in[1];
    const float* b1   = (const float*)d_in[2];
    const float* wga  = (const float*)d_in[3];
    const float* wgb  = (const float*)d_in[4];
    const float* wa   = (const float*)d_in[5];
    const float* wb   = (const float*)d_in[6];
    const float* g2   = (const float*)d_in[7];
    const float* b2   = (const float*)d_in[8];
    const float* wout = (const float*)d_in[9];
    const float* wg   = (const float*)d_in[10];

    cudaFuncSetAttribute(k_proj, cudaFuncAttributeMaxDynamicSharedMemorySize, 139264);
    cudaFuncSetAttribute(k_tri,  cudaFuncAttributeMaxDynamicSharedMemorySize, 73728);
    cudaFuncSetAttribute(k_out,  cudaFuncAttributeMaxDynamicSharedMemorySize, 139264);

    k_proj<<<RTOT / 128, 256, 139264>>>(x, g1, b1, wga, wgb, wa, wb, wg);

    dim3 grid(NN / 128, NN / 128, CZc);
    k_tri<<<grid, 256, 73728>>>();

    k_out<<<RTOT / 128, 256, 139264>>>(g2, b2, wout, (float*)d_out);
}